// round 13
// baseline (speedup 1.0000x reference)
#include <cuda_runtime.h>
#include <cuda_bf16.h>
#include <math.h>

// p1,p2 [8,64,128,128] f32 -> 4x4 avgpool -> 8192 rows x 64 ch, L2-normalized.
// loss = (||Caa||F^2 + ||Cbb||F^2 - 2||Cab||F^2) / N^2,  C.. = X^T Y (64x64).
// R9 design: k_main 256 blocks @ occ 2 (16 warps/SM); k_fin's final combine
// parallelized (R8 showed 8-11us serial 48-load tail on one thread).

#define NROWS 8192
#define NCH   64
#define RT    32              // rows per block (one (b,sh) slab)
#define NBLK  256             // k_main blocks, 2 CTAs/SM -> single wave
#define SPAD  68              // smem pitch (floats)
#define NC2   (NCH * NCH)     // 4096
#define NPART (3 * NC2)       // 12288
#define FBLK  48              // finalize blocks (48*256 == NPART)

// Scratch (__device__ globals: allocation-free rule)
__device__ float        g_part[NBLK][NPART];   // per-block covariance partials
__device__ double       g_bsum[FBLK];          // per-block signed-square sums
__device__ unsigned int g_ctr = 0;             // last-block ticket (reset each run)

// 16B-granular offset shift (keeps float4 alignment; consistent everywhere)
__device__ __forceinline__ int swz(int o) { return o + ((o & 32) >> 3); }

__device__ __forceinline__ unsigned long long dup2(float x) {
    unsigned long long r;
    asm("mov.b64 %0, {%1, %1};" : "=l"(r) : "f"(x));
    return r;
}
__device__ __forceinline__ void fma2(unsigned long long& d,
                                     unsigned long long a, unsigned long long b) {
    asm("fma.rn.f32x2 %0, %1, %2, %0;" : "+l"(d) : "l"(a), "l"(b));
}

// ---------------------------------------------------------------------------
// K1: fused pool + normalize + covariance partials.
// Block bid -> (b = bid>>5, sh = bid&31): 32 pooled rows (sw = 0..31).
// ---------------------------------------------------------------------------
__global__ void __launch_bounds__(256, 2) k_main(const float* __restrict__ p1,
                                                 const float* __restrict__ p2) {
    __shared__ float sA[RT][SPAD];
    __shared__ float sB[RT][SPAD];
    __shared__ float sinv[2][RT];

    int bid = blockIdx.x;
    int b   = bid >> 5;
    int sh  = bid & 31;
    int tid = threadIdx.x;

    // ---- pool: thread = (c = tid>>2, h = tid&3), pixel row 4*sh + h ----
    {
        int c = tid >> 2, h = tid & 3;
        size_t base = (((size_t)(b * 64 + c) * 128) + (size_t)(4 * sh + h)) * 128;
        const float4* a4 = reinterpret_cast<const float4*>(p1 + base);
        const float4* b4 = reinterpret_cast<const float4*>(p2 + base);

        float s[32];
#pragma unroll
        for (int g = 0; g < 32; g++) { float4 v = a4[g]; s[g] = (v.x + v.y) + (v.z + v.w); }
#pragma unroll
        for (int g = 0; g < 32; g++) {
            s[g] += __shfl_xor_sync(0xffffffffu, s[g], 1);
            s[g] += __shfl_xor_sync(0xffffffffu, s[g], 2);
        }
        if (h == 0) {
#pragma unroll
            for (int g = 0; g < 32; g++) sA[g][swz(c)] = s[g] * 0.0625f;
        }
#pragma unroll
        for (int g = 0; g < 32; g++) { float4 v = b4[g]; s[g] = (v.x + v.y) + (v.z + v.w); }
#pragma unroll
        for (int g = 0; g < 32; g++) {
            s[g] += __shfl_xor_sync(0xffffffffu, s[g], 1);
            s[g] += __shfl_xor_sync(0xffffffffu, s[g], 2);
        }
        if (h == 0) {
#pragma unroll
            for (int g = 0; g < 32; g++) sB[g][swz(c)] = s[g] * 0.0625f;
        }
    }
    __syncthreads();

    // ---- row L2 norms: (input = tid>>7, row = (tid>>2)&31, q = tid&3) ----
    {
        int input = tid >> 7, row = (tid >> 2) & 31, q = tid & 3;
        const float (*T)[SPAD] = input ? sB : sA;
        float ss = 0.f;
#pragma unroll
        for (int i = 0; i < 16; i++) {
            float v = T[row][swz(q * 16 + i)];
            ss = fmaf(v, v, ss);
        }
        ss += __shfl_xor_sync(0xffffffffu, ss, 1);
        ss += __shfl_xor_sync(0xffffffffu, ss, 2);
        if (q == 0)
            sinv[input][row] = 1.f / fmaxf(sqrtf(ss), 1e-8f);   // reference eps clamp
    }
    __syncthreads();

    // ---- rescale in place ----
#pragma unroll
    for (int k = tid; k < RT * NCH; k += 256) {
        int row = k >> 6, c = k & 63;
        sA[row][swz(c)] *= sinv[0][row];
    }
#pragma unroll
    for (int k = tid; k < RT * NCH; k += 256) {
        int row = k >> 6, c = k & 63;
        sB[row][swz(c)] *= sinv[1][row];
    }
    __syncthreads();

    // ---- covariance: 16x16 thread grid, each thread 4(i) x 4(j) x 3 mats ----
    int tx = tid & 15, ty = tid >> 4;
    int i0 = ty * 4, j0 = tx * 4;
    int i0s = swz(i0), j0s = swz(j0);

    unsigned long long caa[4][2] = {}, cbb[4][2] = {}, cab[4][2] = {};

#pragma unroll 4
    for (int r = 0; r < RT; r++) {
        float4 ai4 = *reinterpret_cast<const float4*>(&sA[r][i0s]);
        float4 bi4 = *reinterpret_cast<const float4*>(&sB[r][i0s]);
        ulonglong2 aj2 = *reinterpret_cast<const ulonglong2*>(&sA[r][j0s]);
        ulonglong2 bj2 = *reinterpret_cast<const ulonglong2*>(&sB[r][j0s]);
        unsigned long long aj[2] = {aj2.x, aj2.y};
        unsigned long long bj[2] = {bj2.x, bj2.y};
        float ai[4] = {ai4.x, ai4.y, ai4.z, ai4.w};
        float bi[4] = {bi4.x, bi4.y, bi4.z, bi4.w};
#pragma unroll
        for (int ii = 0; ii < 4; ii++) {
            unsigned long long ad = dup2(ai[ii]);
            unsigned long long bd = dup2(bi[ii]);
#pragma unroll
            for (int q = 0; q < 2; q++) {
                fma2(caa[ii][q], ad, aj[q]);
                fma2(cbb[ii][q], bd, bj[q]);
                fma2(cab[ii][q], ad, bj[q]);
            }
        }
    }

    // ---- store partials (packed pair == consecutive j floats; 16B stores) ----
    float* base = g_part[bid];
#pragma unroll
    for (int ii = 0; ii < 4; ii++) {
        int ro = (i0 + ii) * NCH + j0;
        *reinterpret_cast<ulonglong2*>(base + 0 * NC2 + ro) = make_ulonglong2(caa[ii][0], caa[ii][1]);
        *reinterpret_cast<ulonglong2*>(base + 1 * NC2 + ro) = make_ulonglong2(cbb[ii][0], cbb[ii][1]);
        *reinterpret_cast<ulonglong2*>(base + 2 * NC2 + ro) = make_ulonglong2(cab[ii][0], cab[ii][1]);
    }
}

// ---------------------------------------------------------------------------
// K2: fold 256 partials per entry (two independent chains), signed square,
//     block tree-sum, then PARALLEL last-done combine: whole block loads the
//     48 per-block sums at once (one L2 latency, not 48 serial) and reduces.
//     Deterministic order; ticket self-resets for graph replay.
// ---------------------------------------------------------------------------
__global__ void __launch_bounds__(256) k_fin(float* __restrict__ out) {
    __shared__ double red[256];
    __shared__ int is_last;
    int tid = threadIdx.x;
    int g = blockIdx.x * 256 + tid;          // 0..12287, coalesced across k

    const float* __restrict__ part = &g_part[0][0];
    float s0 = 0.f, s1 = 0.f;
#pragma unroll 8
    for (int k = 0; k < NBLK / 2; k++) {
        s0 += part[(size_t)k * NPART + g];
        s1 += part[(size_t)(k + NBLK / 2) * NPART + g];
    }
    float s = s0 + s1;

    double v = (double)s * (double)s;
    if (g >= 2 * NC2) v = -2.0 * v;          // Cab gets -2

    red[tid] = v;
    __syncthreads();
#pragma unroll
    for (int st = 128; st > 0; st >>= 1) {
        if (tid < st) red[tid] += red[tid + st];
        __syncthreads();
    }

    if (tid == 0) {
        g_bsum[blockIdx.x] = red[0];
        __threadfence();                     // publish before ticket
        unsigned int ticket = atomicAdd(&g_ctr, 1u);
        is_last = (ticket == FBLK - 1) ? 1 : 0;
    }
    __syncthreads();

    if (is_last) {
        // all FBLK tickets taken, each preceded by a fence -> g_bsum visible
        __threadfence();
        double v2 = (tid < FBLK) ? g_bsum[tid] : 0.0;   // parallel loads
        red[tid] = v2;
        __syncthreads();
#pragma unroll
        for (int st = 128; st > 0; st >>= 1) {
            if (tid < st) red[tid] += red[tid + st];
            __syncthreads();
        }
        if (tid == 0) {
            out[0] = (float)(red[0] / ((double)NROWS * (double)NROWS));
            g_ctr = 0;                       // reset for next graph replay
        }
    }
}

// ---------------------------------------------------------------------------
extern "C" void kernel_launch(void* const* d_in, const int* in_sizes, int n_in,
                              void* d_out, int out_size) {
    const float* p1 = (const float*)d_in[0];
    const float* p2 = (const float*)d_in[1];
    float* out = (float*)d_out;

    k_main<<<NBLK, 256>>>(p1, p2);   // pool + normalize + cov partials (HBM-bound)
    k_fin<<<FBLK, 256>>>(out);       // fold + signed squares + parallel scalar
}